// round 15
// baseline (speedup 1.0000x reference)
#include <cuda_runtime.h>
#include <cuda_fp16.h>
#include <cstdint>

#define DEVINL __device__ __forceinline__

// ---------------- problem dims ----------------
#define B_SZ   8
#define S_SZ   4096
#define D_IN   1280
#define D_OUT  1280
#define N_L    4
#define R_L    16
#define J_L    64                 /* N_L * R_L */
#define M_ROWS 32768              /* B_SZ * S_SZ */
#define K_TOT  1344               /* D_IN + J_L  */

// ---------------- tiling ----------------
#define KU      16                /* K per unit ktile */
#define NTU     (K_TOT / KU)      /* 84 unit ktiles */
#define NTU_X   (D_IN / KU)       /* 80 */
#define NTM     (NTU / 4)         /* 21 macro-stages (KC=64) in main kernel */
#define STAGES_G 4
#define N_MTILE (M_ROWS / 128)    /* 256 */
#define G_BLOCKS (M_ROWS / 64)    /* 512 */
#define MAIN_BLOCKS ((D_OUT / 128) * N_MTILE)  /* 2560 */

// Pre-swizzled fp16 operand tensors.
//   Xh[mtile][unit][2048 halves] (4KB tiles), Wh[ntile][unit][2048], Ah[unit][1024]
// 16B-chunk layout inside a tile (m = row, h = k>>3):
//   byte = (m>>2)*128 + (((m&3)*2 + (h ^ ((m>>2)&1))) * 16)
// Conflict-free for ldmatrix.x4 and identity cp.async; +16 rows => +512B (parity kept).
// 32-row-aligned sub-blocks byte-contiguous: cofs(r0+m,h) = r0*32 + cofs(m,h), r0%32==0.
__device__ __half Xh[(size_t)N_MTILE * NTU * 2048];
__device__ __half Wh[(size_t)(D_OUT / 128) * NTU * 2048];
__device__ __half Ah[(size_t)NTU_X * 1024];
__device__ int    g_done[N_MTILE];        // per-mtile completion flags (2 = ready)

// ---------------- helpers ----------------
DEVINL uint32_t cofs(int m, int h) {      // 16B-chunk byte offset within one tile
    int line = m >> 2;
    int slot = ((m & 3) * 2) + (h ^ (line & 1));
    return (uint32_t)(line * 128 + slot * 16);
}
DEVINL uint32_t pack2h(float a, float b) {
    __half2 h = __floats2half2_rn(a, b);
    return *reinterpret_cast<uint32_t*>(&h);
}
DEVINL void mma_f16(float c[4], uint32_t a0, uint32_t a1, uint32_t a2, uint32_t a3,
                    uint32_t b0, uint32_t b1) {
    asm volatile(
        "mma.sync.aligned.m16n8k16.row.col.f32.f16.f16.f32 "
        "{%0,%1,%2,%3}, {%4,%5,%6,%7}, {%8,%9}, {%0,%1,%2,%3};"
        : "+f"(c[0]), "+f"(c[1]), "+f"(c[2]), "+f"(c[3])
        : "r"(a0), "r"(a1), "r"(a2), "r"(a3), "r"(b0), "r"(b1));
}
DEVINL void ldsm4(uint32_t r[4], uint32_t addr) {
    asm volatile("ldmatrix.sync.aligned.m8n8.x4.shared.b16 {%0,%1,%2,%3}, [%4];"
                 : "=r"(r[0]), "=r"(r[1]), "=r"(r[2]), "=r"(r[3]) : "r"(addr));
}
DEVINL uint32_t smem_u32(const void* p) {
    uint32_t a;
    asm("{ .reg .u64 t; cvta.to.shared.u64 t, %1; cvt.u32.u64 %0, t; }" : "=r"(a) : "l"(p));
    return a;
}
DEVINL void cp16(uint32_t smem, const void* gptr) {
    asm volatile("cp.async.cg.shared.global [%0], [%1], 16;" :: "r"(smem), "l"(gptr) : "memory");
}
DEVINL void sts8(uint32_t addr, uint32_t a, uint32_t b) {
    asm volatile("st.shared.v2.b32 [%0], {%1,%2};" :: "r"(addr), "r"(a), "r"(b) : "memory");
}
#define CP_COMMIT() asm volatile("cp.async.commit_group;" ::: "memory")
#define CP_WAIT1()  asm volatile("cp.async.wait_group 1;" ::: "memory")
#define CP_WAIT2()  asm volatile("cp.async.wait_group 2;" ::: "memory")

// ============================================================================
// Kernel Z: zero the per-mtile flags (re-run on every graph replay)
// ============================================================================
__global__ void zero_flags_kernel() { g_done[threadIdx.x] = 0; }

// ============================================================================
// Kernel 0b: Wh[nt][kt] from W (kt<80) / Bcat gather (kt>=80)   grid (10, 84)
//   Bcat[o][j] = Bw[j>>4][o][j&15]
// ============================================================================
__global__ void __launch_bounds__(128)
convert_w_kernel(const float* __restrict__ W, const float* __restrict__ Bw)
{
    const int tid = threadIdx.x;
    const int nt = blockIdx.x, kt = blockIdx.y;
    char* dst = (char*)(Wh + ((size_t)nt * NTU + kt) * 2048);
    #pragma unroll
    for (int i = 0; i < 2; i++) {
        int idx = tid + i * 128;
        int m = idx >> 1, h = idx & 1;
        const float4* p;
        if (kt < NTU_X) {
            p = (const float4*)(W + (size_t)(nt * 128 + m) * D_IN + kt * KU + h * 8);
        } else {
            p = (const float4*)(Bw + (size_t)(kt - NTU_X) * (D_OUT * R_L)
                                   + (size_t)(nt * 128 + m) * R_L + h * 8);
        }
        float4 v0 = p[0], v1 = p[1];
        uint4 o = { pack2h(v0.x, v0.y), pack2h(v0.z, v0.w),
                    pack2h(v1.x, v1.y), pack2h(v1.z, v1.w) };
        *(uint4*)(dst + cofs(m, h)) = o;
    }
}

// ============================================================================
// Kernel 0c: Ah[kt] = swizzled fp16(Acat)   (64 rows per tile)   grid (80)
// ============================================================================
__global__ void __launch_bounds__(128)
convert_a_kernel(const float* __restrict__ Acat)
{
    const int tid = threadIdx.x;
    const int kt = blockIdx.x;
    char* dst = (char*)(Ah + (size_t)kt * 1024);
    int m = tid >> 1, h = tid & 1;
    const float4* p = (const float4*)(Acat + (size_t)m * D_IN + kt * KU + h * 8);
    float4 v0 = p[0], v1 = p[1];
    uint4 o = { pack2h(v0.x, v0.y), pack2h(v0.z, v0.w),
                pack2h(v1.x, v1.y), pack2h(v1.z, v1.w) };
    *(uint4*)(dst + cofs(m, h)) = o;
}

// ============================================================================
// MEGA kernel: blocks [0,512) run the fused g body (X convert + LoRA GEMM,
//   streaming Xh); blocks [512, 3072) run the main GEMM, spin-waiting on the
//   per-mtile flag before their first fill.  g blocks have the lowest indices,
//   so they own the first scheduling wave -> guaranteed progress, near-zero
//   spin after the ramp (both sides consume mt in increasing block order).
// ============================================================================
#define G_WB   2048                     /* bytes per warp per stage: A 1KB + B 1KB */
#define G_SB   (4 * G_WB)               /* 8192 per stage */
#define M_STG_B  32768                  /* bytes per macro-stage (A 16KB + B 16KB) */
#define MEGA_SMEM (3 * M_STG_B)         /* 98304 */

__global__ void __launch_bounds__(128, 2)
mega_kernel(const float* __restrict__ X,
            const float* __restrict__ scalings, const float* __restrict__ masks,
            const float* __restrict__ bias, float* __restrict__ out)
{
    extern __shared__ char smc[];
    const int bid  = blockIdx.x;
    const int tid  = threadIdx.x;
    const int lane = tid & 31;
    const int wid  = tid >> 5;
    const int gid  = lane >> 2, tig = lane & 3;
    const uint32_t base = smem_u32(smc);

    if (bid < G_BLOCKS) {
        // ==================== g body ====================
        const int ht   = bid & 1;
        const int mt   = bid >> 1;
        const int moff = (wid & 1) * 32;
        const int noff = (wid >> 1) * 32;
        const int r8   = lane & 7, g8 = lane >> 3;
        const int r0   = ht * 64 + moff;
        const int xr   = lane >> 2, xc = lane & 3;

        const uint32_t wbase = base + (uint32_t)wid * G_WB;
        const uint32_t aAddr0 = wbase + cofs(r8 + (g8 & 1) * 8, g8 >> 1);
        const uint32_t bAddr0 = wbase + 1024u + cofs(r8 + (g8 >> 1) * 8, g8 & 1);

        const float* srcX = X + (size_t)(mt * 128 + r0 + xr) * D_IN + xc * 4;
        const __half* srcB = Ah + noff * 16 + lane * 8;
        char* xhb = (char*)(Xh + (size_t)mt * NTU * 2048) + r0 * 32;
        uint32_t lofs[4];
        #pragma unroll
        for (int i = 0; i < 4; i++) lofs[i] = cofs(i * 8 + xr, xc >> 1) + (xc & 1) * 8;

        float acc[2][4][4];
        #pragma unroll
        for (int mi = 0; mi < 2; mi++)
            #pragma unroll
            for (int ni = 0; ni < 4; ni++)
                #pragma unroll
                for (int q = 0; q < 4; q++) acc[mi][ni][q] = 0.f;

        uint32_t va[3][4][2];            // 3-deep X LDG prefetch (2 CTA/SM here)
        auto ldgcv = [&](int t, int sp) {
            #pragma unroll
            for (int i = 0; i < 4; i++) {
                float4 v = *(const float4*)(srcX + (size_t)(i * 8) * D_IN + t * KU);
                va[sp][i][0] = pack2h(v.x, v.y);
                va[sp][i][1] = pack2h(v.z, v.w);
            }
        };
        auto stsA = [&](int sp, int buf, int t) {
            uint32_t d = wbase + (uint32_t)buf * G_SB;
            char* gd = xhb + (size_t)t * 4096;
            #pragma unroll
            for (int i = 0; i < 4; i++) {
                sts8(d + lofs[i], va[sp][i][0], va[sp][i][1]);
                *(uint2*)(gd + lofs[i]) = make_uint2(va[sp][i][0], va[sp][i][1]);
            }
        };
        auto fill_b = [&](int t, int buf) {
            uint32_t d = wbase + (uint32_t)buf * G_SB + 1024u + (uint32_t)lane * 16u;
            const __half* sb = srcB + (size_t)t * 1024;
            cp16(d,        sb);
            cp16(d + 512u, sb + 256);
        };
        auto domma = [&](int buf) {
            const uint32_t bo = (uint32_t)buf * G_SB;
            uint32_t a[2][4], b[2][4];
            #pragma unroll
            for (int mi = 0; mi < 2; mi++) ldsm4(a[mi], aAddr0 + bo + (uint32_t)mi * 512u);
            #pragma unroll
            for (int nj = 0; nj < 2; nj++) ldsm4(b[nj], bAddr0 + bo + (uint32_t)nj * 512u);
            #pragma unroll
            for (int mi = 0; mi < 2; mi++)
                #pragma unroll
                for (int ni = 0; ni < 4; ni++)
                    mma_f16(acc[mi][ni], a[mi][0], a[mi][1], a[mi][2], a[mi][3],
                            b[ni >> 1][(ni & 1) * 2], b[ni >> 1][(ni & 1) * 2 + 1]);
        };

        #pragma unroll
        for (int t = 0; t < STAGES_G; t++) { fill_b(t, t); CP_COMMIT(); }
        ldgcv(0, 0); ldgcv(1, 1); ldgcv(2, 2);
        int sp = 0;
        for (int t = 0; t < NTU_X; t++) {
            const int buf = t & 3;
            CP_WAIT2();                   // B for stage t resident
            stsA(sp, buf, t);             // A: smem staging + stream to Xh
            __syncwarp();
            if (t + 3 < NTU_X) ldgcv(t + 3, sp);
            if (++sp == 3) sp = 0;
            domma(buf);
            if (t + STAGES_G < NTU_X) fill_b(t + STAGES_G, buf);
            CP_COMMIT();
        }

        // epilogue: coef = scaling * mask, fp16-round, store into Xh ktiles 80..83
        float coef[2][2][2];
        #pragma unroll
        for (int mi = 0; mi < 2; mi++)
            #pragma unroll
            for (int h = 0; h < 2; h++) {
                int m = mt * 128 + r0 + mi * 16 + gid + h * 8;
                int s = m & (S_SZ - 1);
                #pragma unroll
                for (int sl = 0; sl < 2; sl++) {
                    int subj = (noff >> 4) + sl;
                    coef[mi][h][sl] = scalings[subj] * masks[subj * S_SZ + s];
                }
            }
        char* xblk = (char*)(Xh + (size_t)mt * NTU * 2048);
        #pragma unroll
        for (int mi = 0; mi < 2; mi++)
            #pragma unroll
            for (int ni = 0; ni < 4; ni++) {
                int col = noff + ni * 8 + 2 * tig;
                int sl  = (col >> 4) & 1;
                int kt  = NTU_X + (col >> 4);
                int kk  = col & 15;
                #pragma unroll
                for (int h = 0; h < 2; h++) {
                    int rr = r0 + mi * 16 + gid + h * 8;
                    uint32_t v = pack2h(acc[mi][ni][2 * h + 0] * coef[mi][h][sl],
                                        acc[mi][ni][2 * h + 1] * coef[mi][h][sl]);
                    *(uint32_t*)(xblk + (size_t)kt * 4096 + cofs(rr, kk >> 3) + (kk & 7) * 2) = v;
                }
            }

        // signal: all this CTA's Xh writes are done
        __syncthreads();
        if (tid == 0) {
            __threadfence();
            atomicAdd(&g_done[mt], 1);
        }
        return;
    }

    // ==================== main body ====================
    const int bm = bid - G_BLOCKS;
    const int nt = bm % (D_OUT / 128);   // nt fastest: CTAs sharing mt hit Xh in L2
    const int mt = bm / (D_OUT / 128);
    const int moff = (wid & 1) * 64;
    const int noff = (wid >> 1) * 64;
    const int r8   = lane & 7, g8 = lane >> 3;

    // wait for this mtile's Xh tiles (both g halves)
    if (tid == 0) {
        const int* fp = &g_done[mt];
        int v;
        for (;;) {
            asm volatile("ld.acquire.gpu.global.b32 %0, [%1];" : "=r"(v) : "l"(fp));
            if (v >= 2) break;
            __nanosleep(200);
        }
    }
    __syncthreads();

    const uint32_t aAddr0 = base + cofs(moff + r8 + (g8 & 1) * 8, g8 >> 1);
    const uint32_t bAddr0 = base + 16384u + cofs(noff + r8 + (g8 >> 1) * 8, g8 & 1);

    const __half* srcA = Xh + (size_t)mt * NTU * 2048 + tid * 8;
    const __half* srcB = Wh + (size_t)nt * NTU * 2048 + tid * 8;

    float acc[4][8][4];
    #pragma unroll
    for (int mi = 0; mi < 4; mi++)
        #pragma unroll
        for (int ni = 0; ni < 8; ni++)
            #pragma unroll
            for (int q = 0; q < 4; q++) acc[mi][ni][q] = 0.f;

    auto fill = [&](int t2, int buf) {       // units 4*t2 .. 4*t2+3
        uint32_t d = base + (uint32_t)buf * M_STG_B + (uint32_t)tid * 16u;
        const __half* sa = srcA + (size_t)t2 * 8192;
        const __half* sb = srcB + (size_t)t2 * 8192;
        #pragma unroll
        for (int i = 0; i < 8; i++) {
            cp16(d + i * 2048u, sa + i * 1024);
            cp16(d + 16384u + i * 2048u, sb + i * 1024);
        }
    };
    auto loadfrag = [&](uint32_t uo, uint32_t (*a)[4], uint32_t (*b)[4]) {
        #pragma unroll
        for (int mi = 0; mi < 4; mi++)
            ldsm4(a[mi], aAddr0 + uo + (uint32_t)mi * 512u);
        #pragma unroll
        for (int nj = 0; nj < 4; nj++)
            ldsm4(b[nj], bAddr0 + uo + (uint32_t)nj * 512u);
    };
    auto domma = [&](int buf) {
        const uint32_t bo = (uint32_t)buf * M_STG_B;
        uint32_t a[2][4][4], b[2][4][4];
        loadfrag(bo, a[0], b[0]);
        #pragma unroll
        for (int u = 0; u < 4; u++) {
            const int cur = u & 1;
            if (u < 3) loadfrag(bo + (uint32_t)(u + 1) * 4096u, a[cur ^ 1], b[cur ^ 1]);
            #pragma unroll
            for (int mi = 0; mi < 4; mi++)
                #pragma unroll
                for (int ni = 0; ni < 8; ni++)
                    mma_f16(acc[mi][ni],
                            a[cur][mi][0], a[cur][mi][1], a[cur][mi][2], a[cur][mi][3],
                            b[cur][ni >> 1][(ni & 1) * 2], b[cur][ni >> 1][(ni & 1) * 2 + 1]);
        }
    };

    fill(0, 0); CP_COMMIT();
    fill(1, 1); CP_COMMIT();
    for (int t2 = 0; t2 < NTM; t2++) {
        CP_WAIT1();                          // stage t2's group complete (own thread)
        __syncthreads();                     // all threads' stage-t2 data visible
        if (t2 + 2 < NTM) fill(t2 + 2, (t2 + 2) % 3);
        CP_COMMIT();
        domma(t2 % 3);
    }

    // epilogue: + bias, float2 stores
    const int nb = nt * 128, mb = mt * 128;
    #pragma unroll
    for (int ni = 0; ni < 8; ni++) {
        int col = nb + noff + ni * 8 + 2 * tig;
        float2 bb = *(const float2*)(bias + col);
        #pragma unroll
        for (int mi = 0; mi < 4; mi++) {
            int row0 = mb + moff + mi * 16 + gid;
            float2 v0 = { acc[mi][ni][0] + bb.x, acc[mi][ni][1] + bb.y };
            float2 v1 = { acc[mi][ni][2] + bb.x, acc[mi][ni][3] + bb.y };
            *(float2*)(out + (size_t)row0 * D_OUT + col)       = v0;
            *(float2*)(out + (size_t)(row0 + 8) * D_OUT + col) = v1;
        }
    }
}

// ============================================================================
extern "C" void kernel_launch(void* const* d_in, const int* in_sizes, int n_in,
                              void* d_out, int out_size)
{
    (void)in_sizes; (void)n_in; (void)out_size;
    const float* X     = (const float*)d_in[0];
    const float* W     = (const float*)d_in[1];
    const float* bias  = (const float*)d_in[2];
    const float* Acat  = (const float*)d_in[3];   // (N,R,D) flattens to (64,1280)
    const float* Bw    = (const float*)d_in[4];
    const float* scal  = (const float*)d_in[5];
    const float* masks = (const float*)d_in[6];
    float* out = (float*)d_out;

    cudaFuncSetAttribute(mega_kernel,
                         cudaFuncAttributeMaxDynamicSharedMemorySize, MEGA_SMEM);

    zero_flags_kernel<<<1, N_MTILE>>>();
    convert_a_kernel<<<NTU_X, 128>>>(Acat);
    convert_w_kernel<<<dim3(D_OUT / 128, NTU), 128>>>(W, Bw);
    mega_kernel<<<G_BLOCKS + MAIN_BLOCKS, 128, MEGA_SMEM>>>(X, scal, masks, bias, out);
}

// round 16
// speedup vs baseline: 1.1401x; 1.1401x over previous
#include <cuda_runtime.h>
#include <cuda_fp16.h>
#include <cstdint>

#define DEVINL __device__ __forceinline__

// ---------------- problem dims ----------------
#define B_SZ   8
#define S_SZ   4096
#define D_IN   1280
#define D_OUT  1280
#define N_L    4
#define R_L    16
#define J_L    64                 /* N_L * R_L */
#define M_ROWS 32768              /* B_SZ * S_SZ */
#define K_TOT  1344               /* D_IN + J_L  */

// ---------------- tiling ----------------
#define KU      16                /* K per unit ktile */
#define NTU     (K_TOT / KU)      /* 84 unit ktiles */
#define NTU_X   (D_IN / KU)       /* 80 */
#define NTM     (NTU / 4)         /* 21 macro-stages (KC=64) in main kernel */
#define STAGES_M 3
#define STAGES_G 4

// Pre-swizzled fp16 operand tensors.
//   Xh[mtile][unit][2048 halves] (4KB tiles), Wh[ntile][unit][2048], Ah[unit][1024]
// 16B-chunk layout inside a tile (m = row, h = k>>3):
//   byte = (m>>2)*128 + (((m&3)*2 + (h ^ ((m>>2)&1))) * 16)
// Conflict-free for ldmatrix.x4 and identity cp.async; +16 rows => +512B (parity kept).
// 32-row-aligned sub-blocks byte-contiguous: cofs(r0+m,h) = r0*32 + cofs(m,h), r0%32==0.
__device__ __half Xh[(size_t)(M_ROWS / 128) * NTU * 2048];
__device__ __half Wh[(size_t)(D_OUT / 128) * NTU * 2048];
__device__ __half Ah[(size_t)NTU_X * 1024];

// ---------------- helpers ----------------
DEVINL uint32_t cofs(int m, int h) {      // 16B-chunk byte offset within one tile
    int line = m >> 2;
    int slot = ((m & 3) * 2) + (h ^ (line & 1));
    return (uint32_t)(line * 128 + slot * 16);
}
DEVINL uint32_t pack2h(float a, float b) {
    __half2 h = __floats2half2_rn(a, b);
    return *reinterpret_cast<uint32_t*>(&h);
}
DEVINL void mma_f16(float c[4], uint32_t a0, uint32_t a1, uint32_t a2, uint32_t a3,
                    uint32_t b0, uint32_t b1) {
    asm volatile(
        "mma.sync.aligned.m16n8k16.row.col.f32.f16.f16.f32 "
        "{%0,%1,%2,%3}, {%4,%5,%6,%7}, {%8,%9}, {%0,%1,%2,%3};"
        : "+f"(c[0]), "+f"(c[1]), "+f"(c[2]), "+f"(c[3])
        : "r"(a0), "r"(a1), "r"(a2), "r"(a3), "r"(b0), "r"(b1));
}
DEVINL void ldsm4(uint32_t r[4], uint32_t addr) {
    asm volatile("ldmatrix.sync.aligned.m8n8.x4.shared.b16 {%0,%1,%2,%3}, [%4];"
                 : "=r"(r[0]), "=r"(r[1]), "=r"(r[2]), "=r"(r[3]) : "r"(addr));
}
DEVINL uint32_t smem_u32(const void* p) {
    uint32_t a;
    asm("{ .reg .u64 t; cvta.to.shared.u64 t, %1; cvt.u32.u64 %0, t; }" : "=r"(a) : "l"(p));
    return a;
}
DEVINL void cp16(uint32_t smem, const void* gptr) {
    asm volatile("cp.async.cg.shared.global [%0], [%1], 16;" :: "r"(smem), "l"(gptr) : "memory");
}
#define CP_COMMIT() asm volatile("cp.async.commit_group;" ::: "memory")
#define CP_WAIT1()  asm volatile("cp.async.wait_group 1;" ::: "memory")
#define CP_WAIT2()  asm volatile("cp.async.wait_group 2;" ::: "memory")

// ============================================================================
// Kernel 0a: Xh[mt][kt<80] = swizzled fp16(X)     grid (256, 80), 128 thr
// ============================================================================
__global__ void __launch_bounds__(128)
convert_x_kernel(const float* __restrict__ X)
{
    const int tid = threadIdx.x;
    const int mt = blockIdx.x, kt = blockIdx.y;
    char* dst = (char*)(Xh + ((size_t)mt * NTU + kt) * 2048);
    #pragma unroll
    for (int i = 0; i < 2; i++) {
        int idx = tid + i * 128;
        int m = idx >> 1, h = idx & 1;
        const float4* p = (const float4*)(X + (size_t)(mt * 128 + m) * D_IN + kt * KU + h * 8);
        float4 v0 = p[0], v1 = p[1];
        uint4 o = { pack2h(v0.x, v0.y), pack2h(v0.z, v0.w),
                    pack2h(v1.x, v1.y), pack2h(v1.z, v1.w) };
        *(uint4*)(dst + cofs(m, h)) = o;
    }
}

// ============================================================================
// Kernel 0b: Wh[nt][kt] from W (kt<80) / Bcat gather (kt>=80)   grid (10, 84)
//   Bcat[o][j] = Bw[j>>4][o][j&15]
// ============================================================================
__global__ void __launch_bounds__(128)
convert_w_kernel(const float* __restrict__ W, const float* __restrict__ Bw)
{
    const int tid = threadIdx.x;
    const int nt = blockIdx.x, kt = blockIdx.y;
    char* dst = (char*)(Wh + ((size_t)nt * NTU + kt) * 2048);
    #pragma unroll
    for (int i = 0; i < 2; i++) {
        int idx = tid + i * 128;
        int m = idx >> 1, h = idx & 1;
        const float4* p;
        if (kt < NTU_X) {
            p = (const float4*)(W + (size_t)(nt * 128 + m) * D_IN + kt * KU + h * 8);
        } else {
            p = (const float4*)(Bw + (size_t)(kt - NTU_X) * (D_OUT * R_L)
                                   + (size_t)(nt * 128 + m) * R_L + h * 8);
        }
        float4 v0 = p[0], v1 = p[1];
        uint4 o = { pack2h(v0.x, v0.y), pack2h(v0.z, v0.w),
                    pack2h(v1.x, v1.y), pack2h(v1.z, v1.w) };
        *(uint4*)(dst + cofs(m, h)) = o;
    }
}

// ============================================================================
// Kernel 0c: Ah[kt] = swizzled fp16(Acat)   (64 rows per tile)   grid (80)
// ============================================================================
__global__ void __launch_bounds__(128)
convert_a_kernel(const float* __restrict__ Acat)
{
    const int tid = threadIdx.x;
    const int kt = blockIdx.x;
    char* dst = (char*)(Ah + (size_t)kt * 1024);
    int m = tid >> 1, h = tid & 1;
    const float4* p = (const float4*)(Acat + (size_t)m * D_IN + kt * KU + h * 8);
    float4 v0 = p[0], v1 = p[1];
    uint4 o = { pack2h(v0.x, v0.y), pack2h(v0.z, v0.w),
                pack2h(v1.x, v1.y), pack2h(v1.z, v1.w) };
    *(uint4*)(dst + cofs(m, h)) = o;
}

// ============================================================================
// Kernel 1: LoRA activations -> Xh ktiles 80..83   [barrier-free, warp-private]
//   g[m][j] = scaling[j>>4]*mask[j>>4][m&4095] * (x[m].Acat[j]), fp16-rounded.
//   512 CTAs of 64 rows, 4 warps (2m x 2n), warp tile 32x32, 4 CTAs/SM.
//   (R13 version — measured best; reads Xh, identity cp.async.)
// ============================================================================
#define G_WB   2048                     /* bytes per warp per stage: A 1KB + B 1KB */
#define G_SB   (4 * G_WB)               /* 8192 per stage */
#define G_SMEM (STAGES_G * G_SB)        /* 32768 */
__global__ void __launch_bounds__(128, 4)
lora_g_kernel(const float* __restrict__ scalings, const float* __restrict__ masks)
{
    extern __shared__ char smc[];
    const int tid  = threadIdx.x;
    const int ht   = blockIdx.x & 1;      // which 64-row half of the 128-row tile
    const int mt   = blockIdx.x >> 1;
    const int lane = tid & 31;
    const int wid  = tid >> 5;
    const int gid  = lane >> 2, tig = lane & 3;
    const int moff = (wid & 1) * 32;      // local row offset within the 64-row half
    const int noff = (wid >> 1) * 32;
    const int r8   = lane & 7, g8 = lane >> 3;

    const uint32_t base  = smem_u32(smc);
    const uint32_t wbase = base + (uint32_t)wid * G_WB;
    const uint32_t aAddr0 = wbase + cofs(r8 + (g8 & 1) * 8, g8 >> 1);
    const uint32_t bAddr0 = wbase + 1024u + cofs(r8 + (g8 >> 1) * 8, g8 & 1);

    // 32-row-aligned blocks are contiguous: rows [r0,r0+32) -> bytes [r0*32,+1024)
    const __half* srcA = Xh + (size_t)mt * NTU * 2048 + (ht * 64 + moff) * 16 + lane * 8;
    const __half* srcB = Ah + noff * 16 + lane * 8;

    float acc[2][4][4];
    #pragma unroll
    for (int mi = 0; mi < 2; mi++)
        #pragma unroll
        for (int ni = 0; ni < 4; ni++)
            #pragma unroll
            for (int q = 0; q < 4; q++) acc[mi][ni][q] = 0.f;

    auto fill = [&](int t, int buf) {
        uint32_t d = wbase + (uint32_t)buf * G_SB + (uint32_t)lane * 16u;
        const __half* sa = srcA + (size_t)t * 2048;
        const __half* sb = srcB + (size_t)t * 1024;
        cp16(d,          sa);
        cp16(d + 512u,   sa + 256);
        cp16(d + 1024u,  sb);
        cp16(d + 1536u,  sb + 256);
    };
    auto domma = [&](int buf) {
        const uint32_t bo = (uint32_t)buf * G_SB;
        uint32_t a[2][4], b[2][4];
        #pragma unroll
        for (int mi = 0; mi < 2; mi++) ldsm4(a[mi], aAddr0 + bo + (uint32_t)mi * 512u);
        #pragma unroll
        for (int nj = 0; nj < 2; nj++) ldsm4(b[nj], bAddr0 + bo + (uint32_t)nj * 512u);
        #pragma unroll
        for (int mi = 0; mi < 2; mi++)
            #pragma unroll
            for (int ni = 0; ni < 4; ni++)
                mma_f16(acc[mi][ni], a[mi][0], a[mi][1], a[mi][2], a[mi][3],
                        b[ni >> 1][(ni & 1) * 2], b[ni >> 1][(ni & 1) * 2 + 1]);
    };

    #pragma unroll
    for (int t = 0; t < STAGES_G; t++) { fill(t, t); CP_COMMIT(); }
    for (int t = 0; t < NTU_X; t++) {
        CP_WAIT2();
        domma(t & 3);
        if (t + STAGES_G < NTU_X) fill(t + STAGES_G, t & 3);
        CP_COMMIT();
    }

    // epilogue: coef = scaling * mask, fp16-round, store into Xh ktiles 80..83
    float coef[2][2][2];
    #pragma unroll
    for (int mi = 0; mi < 2; mi++)
        #pragma unroll
        for (int h = 0; h < 2; h++) {
            int m = mt * 128 + ht * 64 + moff + mi * 16 + gid + h * 8;
            int s = m & (S_SZ - 1);
            #pragma unroll
            for (int sl = 0; sl < 2; sl++) {
                int subj = (noff >> 4) + sl;
                coef[mi][h][sl] = scalings[subj] * masks[subj * S_SZ + s];
            }
        }
    char* xblk = (char*)(Xh + (size_t)mt * NTU * 2048);
    #pragma unroll
    for (int mi = 0; mi < 2; mi++)
        #pragma unroll
        for (int ni = 0; ni < 4; ni++) {
            int col = noff + ni * 8 + 2 * tig;     // 0..63
            int sl  = (col >> 4) & 1;
            int kt  = NTU_X + (col >> 4);
            int kk  = col & 15;
            #pragma unroll
            for (int h = 0; h < 2; h++) {
                int rr = ht * 64 + moff + mi * 16 + gid + h * 8;   // row in 128-row tile
                uint32_t v = pack2h(acc[mi][ni][2 * h + 0] * coef[mi][h][sl],
                                    acc[mi][ni][2 * h + 1] * coef[mi][h][sl]);
                *(uint32_t*)(xblk + (size_t)kt * 4096 + cofs(rr, kk >> 3) + (kk & 7) * 2) = v;
            }
        }
}

// ============================================================================
// Kernel 2: out = [X|g] @ [W|Bcat]^T + bias   (K = 1344, fp16 MMA)
//   256 thr, 128x128 tile, 8 warps (2m x 4n), warp tile 64x32.
//   16 warps/SM (4/SMSP) at 2 CTAs/SM -> better issue-hole coverage.
//   KC=64 macro-stages (21), 3-deep, 96KB smem.  No frag double-buffer
//   (proven neutral; dropping it keeps regs ~110 so 2 CTAs fit the RF).
// ============================================================================
#define M_STG_B  32768                        /* bytes per macro-stage (A 16KB + B 16KB) */
#define M_SMEM   (STAGES_M * M_STG_B)         /* 98304 */
__global__ void __launch_bounds__(256, 2)
lora_main_kernel(const float* __restrict__ bias, float* __restrict__ out)
{
    extern __shared__ char smc[];
    const int tid  = threadIdx.x;
    const int nt   = blockIdx.x;          // x fastest: CTAs sharing mt hit Xh in L2
    const int mt   = blockIdx.y;
    const int lane = tid & 31;
    const int wid  = tid >> 5;            // 0..7
    const int gid  = lane >> 2, tig = lane & 3;
    const int moff = (wid & 1) * 64;
    const int noff = (wid >> 1) * 32;
    const int r8   = lane & 7, g8 = lane >> 3;

    const uint32_t base = smem_u32(smc);
    // stage layout: [A: 4 unit tiles, 16KB][B: 4 unit tiles, 16KB]
    const uint32_t aAddr0 = base + cofs(moff + r8 + (g8 & 1) * 8, g8 >> 1);
    const uint32_t bAddr0 = base + 16384u + cofs(noff + r8 + (g8 >> 1) * 8, g8 & 1);

    const __half* srcA = Xh + (size_t)mt * NTU * 2048 + tid * 8;
    const __half* srcB = Wh + (size_t)nt * NTU * 2048 + tid * 8;

    float acc[4][4][4];
    #pragma unroll
    for (int mi = 0; mi < 4; mi++)
        #pragma unroll
        for (int ni = 0; ni < 4; ni++)
            #pragma unroll
            for (int q = 0; q < 4; q++) acc[mi][ni][q] = 0.f;

    auto fill = [&](int t2, int buf) {       // units 4*t2 .. 4*t2+3
        uint32_t d = base + (uint32_t)buf * M_STG_B + (uint32_t)tid * 16u;
        const __half* sa = srcA + (size_t)t2 * 8192;
        const __half* sb = srcB + (size_t)t2 * 8192;
        #pragma unroll
        for (int u = 0; u < 4; u++) {        // 256 thr x 16B cover one 4KB unit tile
            cp16(d + (uint32_t)u * 4096u, sa + u * 2048);
            cp16(d + 16384u + (uint32_t)u * 4096u, sb + u * 2048);
        }
    };
    auto domma = [&](int buf) {
        const uint32_t bo = (uint32_t)buf * M_STG_B;
        #pragma unroll
        for (int u = 0; u < 4; u++) {
            const uint32_t uo = bo + (uint32_t)u * 4096u;
            uint32_t a[4][4], b[2][4];
            #pragma unroll
            for (int mi = 0; mi < 4; mi++)
                ldsm4(a[mi], aAddr0 + uo + (uint32_t)mi * 512u);
            #pragma unroll
            for (int nj = 0; nj < 2; nj++)
                ldsm4(b[nj], bAddr0 + uo + (uint32_t)nj * 512u);
            #pragma unroll
            for (int mi = 0; mi < 4; mi++)
                #pragma unroll
                for (int ni = 0; ni < 4; ni++)
                    mma_f16(acc[mi][ni], a[mi][0], a[mi][1], a[mi][2], a[mi][3],
                            b[ni >> 1][(ni & 1) * 2], b[ni >> 1][(ni & 1) * 2 + 1]);
        }
    };

    fill(0, 0); CP_COMMIT();
    fill(1, 1); CP_COMMIT();
    for (int t2 = 0; t2 < NTM; t2++) {
        CP_WAIT1();                          // stage t2's group complete (own thread)
        __syncthreads();                     // all threads' stage-t2 data visible
        if (t2 + 2 < NTM) fill(t2 + 2, (t2 + 2) % STAGES_M);
        CP_COMMIT();
        domma(t2 % STAGES_M);
    }

    // epilogue: + bias, float2 stores
    const int nb = nt * 128, mb = mt * 128;
    #pragma unroll
    for (int ni = 0; ni < 4; ni++) {
        int col = nb + noff + ni * 8 + 2 * tig;
        float2 bb = *(const float2*)(bias + col);
        #pragma unroll
        for (int mi = 0; mi < 4; mi++) {
            int row0 = mb + moff + mi * 16 + gid;
            float2 v0 = { acc[mi][ni][0] + bb.x, acc[mi][ni][1] + bb.y };
            float2 v1 = { acc[mi][ni][2] + bb.x, acc[mi][ni][3] + bb.y };
            *(float2*)(out + (size_t)row0 * D_OUT + col)       = v0;
            *(float2*)(out + (size_t)(row0 + 8) * D_OUT + col) = v1;
        }
    }
}

// ============================================================================
extern "C" void kernel_launch(void* const* d_in, const int* in_sizes, int n_in,
                              void* d_out, int out_size)
{
    (void)in_sizes; (void)n_in; (void)out_size;
    const float* X     = (const float*)d_in[0];
    const float* W     = (const float*)d_in[1];
    const float* bias  = (const float*)d_in[2];
    const float* Acat  = (const float*)d_in[3];   // (N,R,D) flattens to (64,1280)
    const float* Bw    = (const float*)d_in[4];
    const float* scal  = (const float*)d_in[5];
    const float* masks = (const float*)d_in[6];
    float* out = (float*)d_out;

    cudaFuncSetAttribute(lora_g_kernel,
                         cudaFuncAttributeMaxDynamicSharedMemorySize, G_SMEM);
    cudaFuncSetAttribute(lora_main_kernel,
                         cudaFuncAttributeMaxDynamicSharedMemorySize, M_SMEM);

    convert_x_kernel<<<dim3(M_ROWS / 128, NTU_X), 128>>>(X);
    convert_w_kernel<<<dim3(D_OUT / 128, NTU), 128>>>(W, Bw);
    convert_a_kernel<<<NTU_X, 128>>>(Acat);
    lora_g_kernel<<<M_ROWS / 64, 128, G_SMEM>>>(scal, masks);
    lora_main_kernel<<<dim3(D_OUT / 128, M_ROWS / 128), 256, M_SMEM>>>(bias, out);
}

// round 17
// speedup vs baseline: 1.1627x; 1.0199x over previous
#include <cuda_runtime.h>
#include <cuda_fp16.h>
#include <cstdint>

#define DEVINL __device__ __forceinline__

// ---------------- problem dims ----------------
#define B_SZ   8
#define S_SZ   4096
#define D_IN   1280
#define D_OUT  1280
#define N_L    4
#define R_L    16
#define J_L    64                 /* N_L * R_L */
#define M_ROWS 32768              /* B_SZ * S_SZ */
#define K_TOT  1344               /* D_IN + J_L  */

// ---------------- tiling ----------------
#define KU      16                /* K per unit ktile */
#define NTU     (K_TOT / KU)      /* 84 unit ktiles */
#define NTU_X   (D_IN / KU)       /* 80 */
#define NTM     (NTU / 4)         /* 21 macro-stages (KC=64) in main kernel */
#define STAGES_M 3
#define STAGES_G 4
#define N_MTILE (M_ROWS / 128)    /* 256 */

// Pre-swizzled fp16 operand tensors.
//   Xh[mtile][unit][2048 halves] (4KB tiles), Wh[ntile][unit][2048], Ah[unit][1024]
// 16B-chunk layout inside a tile (m = row, h = k>>3):
//   byte = (m>>2)*128 + (((m&3)*2 + (h ^ ((m>>2)&1))) * 16)
// Conflict-free for ldmatrix.x4 and identity cp.async; +16 rows => +512B (parity kept).
// 32-row-aligned sub-blocks byte-contiguous: cofs(r0+m,h) = r0*32 + cofs(m,h), r0%32==0.
__device__ __half Xh[(size_t)N_MTILE * NTU * 2048];
__device__ __half Wh[(size_t)(D_OUT / 128) * NTU * 2048];
__device__ __half Ah[(size_t)NTU_X * 1024];

// ---------------- helpers ----------------
DEVINL uint32_t cofs(int m, int h) {      // 16B-chunk byte offset within one tile
    int line = m >> 2;
    int slot = ((m & 3) * 2) + (h ^ (line & 1));
    return (uint32_t)(line * 128 + slot * 16);
}
DEVINL uint32_t pack2h(float a, float b) {
    __half2 h = __floats2half2_rn(a, b);
    return *reinterpret_cast<uint32_t*>(&h);
}
DEVINL void mma_f16(float c[4], uint32_t a0, uint32_t a1, uint32_t a2, uint32_t a3,
                    uint32_t b0, uint32_t b1) {
    asm volatile(
        "mma.sync.aligned.m16n8k16.row.col.f32.f16.f16.f32 "
        "{%0,%1,%2,%3}, {%4,%5,%6,%7}, {%8,%9}, {%0,%1,%2,%3};"
        : "+f"(c[0]), "+f"(c[1]), "+f"(c[2]), "+f"(c[3])
        : "r"(a0), "r"(a1), "r"(a2), "r"(a3), "r"(b0), "r"(b1));
}
DEVINL void ldsm4(uint32_t r[4], uint32_t addr) {
    asm volatile("ldmatrix.sync.aligned.m8n8.x4.shared.b16 {%0,%1,%2,%3}, [%4];"
                 : "=r"(r[0]), "=r"(r[1]), "=r"(r[2]), "=r"(r[3]) : "r"(addr));
}
DEVINL uint32_t smem_u32(const void* p) {
    uint32_t a;
    asm("{ .reg .u64 t; cvta.to.shared.u64 t, %1; cvt.u32.u64 %0, t; }" : "=r"(a) : "l"(p));
    return a;
}
DEVINL void cp16(uint32_t smem, const void* gptr) {
    asm volatile("cp.async.cg.shared.global [%0], [%1], 16;" :: "r"(smem), "l"(gptr) : "memory");
}
#define CP_COMMIT() asm volatile("cp.async.commit_group;" ::: "memory")
#define CP_WAIT1()  asm volatile("cp.async.wait_group 1;" ::: "memory")
#define CP_WAIT2()  asm volatile("cp.async.wait_group 2;" ::: "memory")

// ============================================================================
// Kernel 0 (merged converts): one launch.
//   blocks [0, 5120):         X -> Xh  (4 ktiles/block, 8 LDG.128 in flight)
//   blocks [5120, 5330):      W/Bcat -> Wh (4 ktiles/block)
//   blocks [5330, 5350):      Acat -> Ah  (4 ktiles/block)
// ============================================================================
#define CVX_BLOCKS (N_MTILE * (NTU_X / 4))      /* 256*20 = 5120 */
#define CVW_BLOCKS ((D_OUT / 128) * (NTU / 4))  /* 10*21  = 210  */
#define CVA_BLOCKS (NTU_X / 4)                  /* 20 */
#define CV_TOTAL   (CVX_BLOCKS + CVW_BLOCKS + CVA_BLOCKS)

__global__ void __launch_bounds__(128)
convert_all_kernel(const float* __restrict__ X, const float* __restrict__ W,
                   const float* __restrict__ Bw, const float* __restrict__ Acat)
{
    const int tid = threadIdx.x;
    const int b = blockIdx.x;

    if (b < CVX_BLOCKS) {
        const int mt = b / (NTU_X / 4), ktg = b % (NTU_X / 4);
        float4 v[4][2][2];                // [j][i][pair]
        #pragma unroll
        for (int j = 0; j < 4; j++)
            #pragma unroll
            for (int i = 0; i < 2; i++) {
                int idx = tid + i * 128;
                int m = idx >> 1, h = idx & 1;
                const float4* p = (const float4*)(X + (size_t)(mt * 128 + m) * D_IN
                                                    + (ktg * 4 + j) * KU + h * 8);
                v[j][i][0] = p[0];
                v[j][i][1] = p[1];
            }
        #pragma unroll
        for (int j = 0; j < 4; j++) {
            char* dst = (char*)(Xh + ((size_t)mt * NTU + ktg * 4 + j) * 2048);
            #pragma unroll
            for (int i = 0; i < 2; i++) {
                int idx = tid + i * 128;
                int m = idx >> 1, h = idx & 1;
                uint4 o = { pack2h(v[j][i][0].x, v[j][i][0].y), pack2h(v[j][i][0].z, v[j][i][0].w),
                            pack2h(v[j][i][1].x, v[j][i][1].y), pack2h(v[j][i][1].z, v[j][i][1].w) };
                *(uint4*)(dst + cofs(m, h)) = o;
            }
        }
        return;
    }
    if (b < CVX_BLOCKS + CVW_BLOCKS) {
        const int b2 = b - CVX_BLOCKS;
        const int nt = b2 / (NTU / 4), ktg = b2 % (NTU / 4);
        #pragma unroll
        for (int j = 0; j < 4; j++) {
            const int kt = ktg * 4 + j;
            char* dst = (char*)(Wh + ((size_t)nt * NTU + kt) * 2048);
            #pragma unroll
            for (int i = 0; i < 2; i++) {
                int idx = tid + i * 128;
                int m = idx >> 1, h = idx & 1;
                const float4* p;
                if (kt < NTU_X) {
                    p = (const float4*)(W + (size_t)(nt * 128 + m) * D_IN + kt * KU + h * 8);
                } else {
                    p = (const float4*)(Bw + (size_t)(kt - NTU_X) * (D_OUT * R_L)
                                           + (size_t)(nt * 128 + m) * R_L + h * 8);
                }
                float4 v0 = p[0], v1 = p[1];
                uint4 o = { pack2h(v0.x, v0.y), pack2h(v0.z, v0.w),
                            pack2h(v1.x, v1.y), pack2h(v1.z, v1.w) };
                *(uint4*)(dst + cofs(m, h)) = o;
            }
        }
        return;
    }
    {
        const int ktg = b - CVX_BLOCKS - CVW_BLOCKS;
        const int m = tid >> 1, h = tid & 1;
        #pragma unroll
        for (int j = 0; j < 4; j++) {
            const int kt = ktg * 4 + j;
            char* dst = (char*)(Ah + (size_t)kt * 1024);
            const float4* p = (const float4*)(Acat + (size_t)m * D_IN + kt * KU + h * 8);
            float4 v0 = p[0], v1 = p[1];
            uint4 o = { pack2h(v0.x, v0.y), pack2h(v0.z, v0.w),
                        pack2h(v1.x, v1.y), pack2h(v1.z, v1.w) };
            *(uint4*)(dst + cofs(m, h)) = o;
        }
    }
}

// ============================================================================
// Kernel 1: LoRA activations -> Xh ktiles 80..83   [barrier-free, warp-private]
//   g[m][j] = scaling[j>>4]*mask[j>>4][m&4095] * (x[m].Acat[j]), fp16-rounded.
//   512 CTAs of 64 rows, 4 warps (2m x 2n), warp tile 32x32, 4 CTAs/SM.
//   mtiles processed in REVERSE order: convert_all leaves the tail of Xh
//   resident in L2, so starting from the last mtile turns cold reads into hits.
// ============================================================================
#define G_WB   2048                     /* bytes per warp per stage: A 1KB + B 1KB */
#define G_SB   (4 * G_WB)               /* 8192 per stage */
#define G_SMEM (STAGES_G * G_SB)        /* 32768 */
__global__ void __launch_bounds__(128, 4)
lora_g_kernel(const float* __restrict__ scalings, const float* __restrict__ masks)
{
    extern __shared__ char smc[];
    const int tid  = threadIdx.x;
    const int ht   = blockIdx.x & 1;      // which 64-row half of the 128-row tile
    const int mt   = (N_MTILE - 1) - (blockIdx.x >> 1);   // reverse order
    const int lane = tid & 31;
    const int wid  = tid >> 5;
    const int gid  = lane >> 2, tig = lane & 3;
    const int moff = (wid & 1) * 32;      // local row offset within the 64-row half
    const int noff = (wid >> 1) * 32;
    const int r8   = lane & 7, g8 = lane >> 3;

    const uint32_t base  = smem_u32(smc);
    const uint32_t wbase = base + (uint32_t)wid * G_WB;
    const uint32_t aAddr0 = wbase + cofs(r8 + (g8 & 1) * 8, g8 >> 1);
    const uint32_t bAddr0 = wbase + 1024u + cofs(r8 + (g8 >> 1) * 8, g8 & 1);

    // 32-row-aligned blocks are contiguous: rows [r0,r0+32) -> bytes [r0*32,+1024)
    const __half* srcA = Xh + (size_t)mt * NTU * 2048 + (ht * 64 + moff) * 16 + lane * 8;
    const __half* srcB = Ah + noff * 16 + lane * 8;

    float acc[2][4][4];
    #pragma unroll
    for (int mi = 0; mi < 2; mi++)
        #pragma unroll
        for (int ni = 0; ni < 4; ni++)
            #pragma unroll
            for (int q = 0; q < 4; q++) acc[mi][ni][q] = 0.f;

    auto fill = [&](int t, int buf) {
        uint32_t d = wbase + (uint32_t)buf * G_SB + (uint32_t)lane * 16u;
        const __half* sa = srcA + (size_t)t * 2048;
        const __half* sb = srcB + (size_t)t * 1024;
        cp16(d,          sa);
        cp16(d + 512u,   sa + 256);
        cp16(d + 1024u,  sb);
        cp16(d + 1536u,  sb + 256);
    };
    auto domma = [&](int buf) {
        const uint32_t bo = (uint32_t)buf * G_SB;
        uint32_t a[2][4], b[2][4];
        #pragma unroll
        for (int mi = 0; mi < 2; mi++) ldsm4(a[mi], aAddr0 + bo + (uint32_t)mi * 512u);
        #pragma unroll
        for (int nj = 0; nj < 2; nj++) ldsm4(b[nj], bAddr0 + bo + (uint32_t)nj * 512u);
        #pragma unroll
        for (int mi = 0; mi < 2; mi++)
            #pragma unroll
            for (int ni = 0; ni < 4; ni++)
                mma_f16(acc[mi][ni], a[mi][0], a[mi][1], a[mi][2], a[mi][3],
                        b[ni >> 1][(ni & 1) * 2], b[ni >> 1][(ni & 1) * 2 + 1]);
    };

    #pragma unroll
    for (int t = 0; t < STAGES_G; t++) { fill(t, t); CP_COMMIT(); }
    for (int t = 0; t < NTU_X; t++) {
        CP_WAIT2();
        domma(t & 3);
        if (t + STAGES_G < NTU_X) fill(t + STAGES_G, t & 3);
        CP_COMMIT();
    }

    // epilogue: coef = scaling * mask, fp16-round, store into Xh ktiles 80..83
    float coef[2][2][2];
    #pragma unroll
    for (int mi = 0; mi < 2; mi++)
        #pragma unroll
        for (int h = 0; h < 2; h++) {
            int m = mt * 128 + ht * 64 + moff + mi * 16 + gid + h * 8;
            int s = m & (S_SZ - 1);
            #pragma unroll
            for (int sl = 0; sl < 2; sl++) {
                int subj = (noff >> 4) + sl;
                coef[mi][h][sl] = scalings[subj] * masks[subj * S_SZ + s];
            }
        }
    char* xblk = (char*)(Xh + (size_t)mt * NTU * 2048);
    #pragma unroll
    for (int mi = 0; mi < 2; mi++)
        #pragma unroll
        for (int ni = 0; ni < 4; ni++) {
            int col = noff + ni * 8 + 2 * tig;     // 0..63
            int sl  = (col >> 4) & 1;
            int kt  = NTU_X + (col >> 4);
            int kk  = col & 15;
            #pragma unroll
            for (int h = 0; h < 2; h++) {
                int rr = ht * 64 + moff + mi * 16 + gid + h * 8;   // row in 128-row tile
                uint32_t v = pack2h(acc[mi][ni][2 * h + 0] * coef[mi][h][sl],
                                    acc[mi][ni][2 * h + 1] * coef[mi][h][sl]);
                *(uint32_t*)(xblk + (size_t)kt * 4096 + cofs(rr, kk >> 3) + (kk & 7) * 2) = v;
            }
        }
}

// ============================================================================
// Kernel 2: out = [X|g] @ [W|Bcat]^T + bias   (K = 1344, fp16 MMA)
//   256 thr, 128x128 tile, 8 warps (2m x 4n), warp tile 64x32.
//   KC=64 macro-stages (21), 3-deep, 96KB smem, 2 CTAs/SM.  (R16 version,
//   measured at its HMMA pacing point — unchanged.)
// ============================================================================
#define M_STG_B  32768                        /* bytes per macro-stage (A 16KB + B 16KB) */
#define M_SMEM   (STAGES_M * M_STG_B)         /* 98304 */
__global__ void __launch_bounds__(256, 2)
lora_main_kernel(const float* __restrict__ bias, float* __restrict__ out)
{
    extern __shared__ char smc[];
    const int tid  = threadIdx.x;
    const int nt   = blockIdx.x;          // x fastest: CTAs sharing mt hit Xh in L2
    const int mt   = blockIdx.y;
    const int lane = tid & 31;
    const int wid  = tid >> 5;            // 0..7
    const int gid  = lane >> 2, tig = lane & 3;
    const int moff = (wid & 1) * 64;
    const int noff = (wid >> 1) * 32;
    const int r8   = lane & 7, g8 = lane >> 3;

    const uint32_t base = smem_u32(smc);
    // stage layout: [A: 4 unit tiles, 16KB][B: 4 unit tiles, 16KB]
    const uint32_t aAddr0 = base + cofs(moff + r8 + (g8 & 1) * 8, g8 >> 1);
    const uint32_t bAddr0 = base + 16384u + cofs(noff + r8 + (g8 >> 1) * 8, g8 & 1);

    const __half* srcA = Xh + (size_t)mt * NTU * 2048 + tid * 8;
    const __half* srcB = Wh + (size_t)nt * NTU * 2048 + tid * 8;

    float acc[4][4][4];
    #pragma unroll
    for (int mi = 0; mi < 4; mi++)
        #pragma unroll
        for (int ni = 0; ni < 4; ni++)
            #pragma unroll
            for (int q = 0; q < 4; q++) acc[mi][ni][q] = 0.f;

    auto fill = [&](int t2, int buf) {       // units 4*t2 .. 4*t2+3
        uint32_t d = base + (uint32_t)buf * M_STG_B + (uint32_t)tid * 16u;
        const __half* sa = srcA + (size_t)t2 * 8192;
        const __half* sb = srcB + (size_t)t2 * 8192;
        #pragma unroll
        for (int u = 0; u < 4; u++) {        // 256 thr x 16B cover one 4KB unit tile
            cp16(d + (uint32_t)u * 4096u, sa + u * 2048);
            cp16(d + 16384u + (uint32_t)u * 4096u, sb + u * 2048);
        }
    };
    auto domma = [&](int buf) {
        const uint32_t bo = (uint32_t)buf * M_STG_B;
        #pragma unroll
        for (int u = 0; u < 4; u++) {
            const uint32_t uo = bo + (uint32_t)u * 4096u;
            uint32_t a[4][4], b[2][4];
            #pragma unroll
            for (int mi = 0; mi < 4; mi++)
                ldsm4(a[mi], aAddr0 + uo + (uint32_t)mi * 512u);
            #pragma unroll
            for (int nj = 0; nj < 2; nj++)
                ldsm4(b[nj], bAddr0 + uo + (uint32_t)nj * 512u);
            #pragma unroll
            for (int mi = 0; mi < 4; mi++)
                #pragma unroll
                for (int ni = 0; ni < 4; ni++)
                    mma_f16(acc[mi][ni], a[mi][0], a[mi][1], a[mi][2], a[mi][3],
                            b[ni >> 1][(ni & 1) * 2], b[ni >> 1][(ni & 1) * 2 + 1]);
        }
    };

    fill(0, 0); CP_COMMIT();
    fill(1, 1); CP_COMMIT();
    for (int t2 = 0; t2 < NTM; t2++) {
        CP_WAIT1();                          // stage t2's group complete (own thread)
        __syncthreads();                     // all threads' stage-t2 data visible
        if (t2 + 2 < NTM) fill(t2 + 2, (t2 + 2) % STAGES_M);
        CP_COMMIT();
        domma(t2 % STAGES_M);
    }

    // epilogue: + bias, float2 stores
    const int nb = nt * 128, mb = mt * 128;
    #pragma unroll
    for (int ni = 0; ni < 4; ni++) {
        int col = nb + noff + ni * 8 + 2 * tig;
        float2 bb = *(const float2*)(bias + col);
        #pragma unroll
        for (int mi = 0; mi < 4; mi++) {
            int row0 = mb + moff + mi * 16 + gid;
            float2 v0 = { acc[mi][ni][0] + bb.x, acc[mi][ni][1] + bb.y };
            float2 v1 = { acc[mi][ni][2] + bb.x, acc[mi][ni][3] + bb.y };
            *(float2*)(out + (size_t)row0 * D_OUT + col)       = v0;
            *(float2*)(out + (size_t)(row0 + 8) * D_OUT + col) = v1;
        }
    }
}

// ============================================================================
extern "C" void kernel_launch(void* const* d_in, const int* in_sizes, int n_in,
                              void* d_out, int out_size)
{
    (void)in_sizes; (void)n_in; (void)out_size;
    const float* X     = (const float*)d_in[0];
    const float* W     = (const float*)d_in[1];
    const float* bias  = (const float*)d_in[2];
    const float* Acat  = (const float*)d_in[3];   // (N,R,D) flattens to (64,1280)
    const float* Bw    = (const float*)d_in[4];
    const float* scal  = (const float*)d_in[5];
    const float* masks = (const float*)d_in[6];
    float* out = (float*)d_out;

    cudaFuncSetAttribute(lora_g_kernel,
                         cudaFuncAttributeMaxDynamicSharedMemorySize, G_SMEM);
    cudaFuncSetAttribute(lora_main_kernel,
                         cudaFuncAttributeMaxDynamicSharedMemorySize, M_SMEM);

    convert_all_kernel<<<CV_TOTAL, 128>>>(X, W, Bw, Acat);
    lora_g_kernel<<<M_ROWS / 64, 128, G_SMEM>>>(scal, masks);
    lora_main_kernel<<<dim3(D_OUT / 128, M_ROWS / 128), 256, M_SMEM>>>(bias, out);
}